// round 6
// baseline (speedup 1.0000x reference)
#include <cuda_runtime.h>
#include <cuda_bf16.h>
#include <math.h>
#include <float.h>

#define B    64
#define P    196
#define ENC  2048
#define H    512
#define E    512
#define A_DIM 512
#define V    30000
#define T    20

#define NS_HC    8   // h0/c0 split-K
#define NS_GATE  4   // gate split-K
#define NS_GATES 12  // gates split-K

// ---------------- scratch (device globals, no allocations) ----------------
__device__ __align__(128) float g_att_enc[B * P * A_DIM];
__device__ __align__(128) float g_part[NS_GATES * B * 4 * H];
__device__ __align__(128) float g_mean[B * ENC];
__device__ __align__(128) float g_h[B * H];
__device__ __align__(128) float g_c[B * H];
__device__ __align__(128) float g_alpha[B * P];
__device__ __align__(128) float g_weighted[B * ENC];
__device__ __align__(128) float g_inp[B * (E + ENC)];
// bf16 hi/lo splits for tensor-core GEMMs
__device__ __align__(128) __nv_bfloat16 g_enc_hi[B * P * ENC];
__device__ __align__(128) __nv_bfloat16 g_enc_lo[B * P * ENC];
__device__ __align__(128) __nv_bfloat16 g_We_hi[A_DIM * ENC];
__device__ __align__(128) __nv_bfloat16 g_We_lo[A_DIM * ENC];
__device__ __align__(128) __nv_bfloat16 g_Wfc_hi[V * H];
__device__ __align__(128) __nv_bfloat16 g_Wfc_lo[V * H];
__device__ __align__(128) __nv_bfloat16 g_h_hi[B * H];
__device__ __align__(128) __nv_bfloat16 g_h_lo[B * H];

__device__ __forceinline__ float sigm(float x) { return 1.f / (1.f + expf(-x)); }

__device__ __forceinline__ unsigned smem_u32(const void* p) {
    unsigned a;
    asm("{ .reg .u64 t; cvta.to.shared.u64 t, %1; cvt.u32.u64 %0, t; }" : "=r"(a) : "l"(p));
    return a;
}
__device__ __forceinline__ void ldm4(unsigned r[4], unsigned addr) {
    asm volatile("ldmatrix.sync.aligned.m8n8.x4.shared.b16 {%0,%1,%2,%3}, [%4];"
        : "=r"(r[0]), "=r"(r[1]), "=r"(r[2]), "=r"(r[3]) : "r"(addr));
}
__device__ __forceinline__ void mma16816(float c[4], const unsigned a[4],
                                         unsigned b0, unsigned b1) {
    asm volatile("mma.sync.aligned.m16n8k16.row.col.f32.bf16.bf16.f32 "
        "{%0,%1,%2,%3}, {%4,%5,%6,%7}, {%8,%9}, {%0,%1,%2,%3};"
        : "+f"(c[0]), "+f"(c[1]), "+f"(c[2]), "+f"(c[3])
        : "r"(a[0]), "r"(a[1]), "r"(a[2]), "r"(a[3]), "r"(b0), "r"(b1));
}

// =====================================================================
//  bf16-split tensor GEMM via mma.sync: C[M,N] = A[M,K] @ W[N,K]^T + bias
//  3 passes: A_hi*B_hi + A_lo*B_hi + A_hi*B_lo (fp32 accumulate).
//  Block: BM x 128, BK=64, 256 threads, 8 warps in 2x4, warp tile (BM/2)x32.
// =====================================================================
template <int BM>
__global__ void __launch_bounds__(256) hmma_k(
    const __nv_bfloat16* __restrict__ Ah, const __nv_bfloat16* __restrict__ Al,
    const __nv_bfloat16* __restrict__ Bh, const __nv_bfloat16* __restrict__ Bl,
    const float* __restrict__ bias, float* __restrict__ C, long long ldc,
    int K, int N, int Mreal)
{
    constexpr int MT = BM / 32;          // m16-tiles per warp
    constexpr int SA = BM * 128;         // bytes per A tile (BK=64 bf16 rows)
    extern __shared__ char sm[];
    char* smAh = sm;
    char* smAl = sm + SA;
    char* smBh = sm + 2 * SA;
    char* smBl = sm + 2 * SA + 16384;
    const unsigned bAh = smem_u32(smAh), bAl = bAh + SA;
    const unsigned bBh = bAh + 2 * SA,  bBl = bBh + 16384;

    const int tid = threadIdx.x, warp = tid >> 5, lane = tid & 31;
    const int m0 = blockIdx.y * BM, n0 = blockIdx.x * 128;
    const int wm = (warp >> 2) * (BM / 2), wn = (warp & 3) * 32;
    const int avalid = min(BM, Mreal - m0);
    const int bvalid = min(128, N - n0);

    float acc[MT][4][4];
#pragma unroll
    for (int mt = 0; mt < MT; mt++)
#pragma unroll
        for (int nt = 0; nt < 4; nt++)
#pragma unroll
            for (int i = 0; i < 4; i++) acc[mt][nt][i] = 0.f;

    for (int kc0 = 0; kc0 < K; kc0 += 64) {
        __syncthreads();
        // load A hi/lo tiles (BM x 64)
        for (int id = tid; id < BM * 8; id += 256) {
            const int row = id >> 3, c = id & 7;
            const int dst = row * 128 + ((c ^ (row & 7)) << 4);
            uint4 vh = make_uint4(0, 0, 0, 0), vl = vh;
            if (row < avalid) {
                const size_t src = (size_t)(m0 + row) * K + kc0 + c * 8;
                vh = *(const uint4*)(Ah + src);
                vl = *(const uint4*)(Al + src);
            }
            *(uint4*)(smAh + dst) = vh;
            *(uint4*)(smAl + dst) = vl;
        }
        // load B hi/lo tiles (128 x 64)
        for (int id = tid; id < 1024; id += 256) {
            const int row = id >> 3, c = id & 7;
            const int dst = row * 128 + ((c ^ (row & 7)) << 4);
            uint4 vh = make_uint4(0, 0, 0, 0), vl = vh;
            if (row < bvalid) {
                const size_t src = (size_t)(n0 + row) * K + kc0 + c * 8;
                vh = *(const uint4*)(Bh + src);
                vl = *(const uint4*)(Bl + src);
            }
            *(uint4*)(smBh + dst) = vh;
            *(uint4*)(smBl + dst) = vl;
        }
        __syncthreads();

#pragma unroll
        for (int kk = 0; kk < 64; kk += 16) {
            unsigned af[MT][4], alf[MT][4], bhf[8], blf[8];
            const int arow = lane & 15;
            const int akc = (kk >> 3) + (lane >> 4);
#pragma unroll
            for (int mt = 0; mt < MT; mt++) {
                const int r = wm + mt * 16 + arow;
                const unsigned off = r * 128 + ((akc ^ (r & 7)) << 4);
                ldm4(af[mt],  bAh + off);
                ldm4(alf[mt], bAl + off);
            }
            const int nl_ = (lane & 7) + ((lane >> 4) << 3);
            const int bkc = (kk >> 3) + ((lane >> 3) & 1);
#pragma unroll
            for (int hf = 0; hf < 2; hf++) {
                const int r = wn + hf * 16 + nl_;
                const unsigned off = r * 128 + ((bkc ^ (r & 7)) << 4);
                ldm4(&bhf[hf * 4], bBh + off);
                ldm4(&blf[hf * 4], bBl + off);
            }
#pragma unroll
            for (int mt = 0; mt < MT; mt++)
#pragma unroll
                for (int nt = 0; nt < 4; nt++) {
                    mma16816(acc[mt][nt], af[mt],  bhf[nt * 2], bhf[nt * 2 + 1]);
                    mma16816(acc[mt][nt], alf[mt], bhf[nt * 2], bhf[nt * 2 + 1]);
                    mma16816(acc[mt][nt], af[mt],  blf[nt * 2], blf[nt * 2 + 1]);
                }
        }
    }

    // epilogue (N even at all call sites -> c0,c0+1 valid together)
#pragma unroll
    for (int mt = 0; mt < MT; mt++)
#pragma unroll
        for (int nt = 0; nt < 4; nt++) {
            const int r0 = m0 + wm + mt * 16 + (lane >> 2);
            const int c0 = n0 + wn + nt * 8 + ((lane & 3) << 1);
            if (c0 < N) {
                const float b0 = bias[c0], b1 = bias[c0 + 1];
                if (r0 < Mreal) {
                    float* p = C + (size_t)r0 * ldc + c0;
                    p[0] = acc[mt][nt][0] + b0;
                    p[1] = acc[mt][nt][1] + b1;
                }
                if (r0 + 8 < Mreal) {
                    float* p = C + (size_t)(r0 + 8) * ldc + c0;
                    p[0] = acc[mt][nt][2] + b0;
                    p[1] = acc[mt][nt][3] + b1;
                }
            }
        }
}

// ---------------- fp32 -> bf16 hi/lo split ----------------
__global__ void split_k(const float* __restrict__ src,
                        __nv_bfloat16* __restrict__ hi, __nv_bfloat16* __restrict__ lo, int n)
{
    const int i = blockIdx.x * 256 + threadIdx.x;
    if (i < n) {
        const float x = src[i];
        const __nv_bfloat16 h = __float2bfloat16(x);
        hi[i] = h;
        lo[i] = __float2bfloat16(x - __bfloat162float(h));
    }
}

// =====================================================================
// gemm64 (fp32 split-K): h0/c0, gate, gates
// =====================================================================
template <int MODE>
__global__ void __launch_bounds__(128) gemm64_k(
    const float* __restrict__ A1, int lda1,
    const float* __restrict__ A2, int lda2,
    const float* __restrict__ W1, int ldw1,
    const float* __restrict__ W2, int ldw2, int K1,
    const float* __restrict__ bias,
    float* __restrict__ C, long long ldc, int N, int kchunk)
{
    __shared__ float As[16][64];
    __shared__ float Ws[16][64];
    const int tid = threadIdx.x;
    const int n0  = blockIdx.x * 64;
    const int s   = blockIdx.y;
    const int k0b = s * kchunk;
    const float* Abase; int ldA;
    const float* Wbase; int ldW;
    if (MODE == 2 && k0b >= K1) { Abase = A2 + (k0b - K1); ldA = lda2; Wbase = W2 + (k0b - K1); ldW = ldw2; }
    else                        { Abase = A1 + k0b;        ldA = lda1; Wbase = W1 + k0b;        ldW = ldw1; }
    const int lr = tid & 63;
    const int lk = (tid >> 6) * 8;
    const int wrow = n0 + lr;
    const float* Ap = Abase + (size_t)lr * ldA + lk;
    const float* Wp = (wrow < N) ? (Wbase + (size_t)wrow * ldW + lk) : nullptr;
    const int tx = tid & 15;
    const int ty = tid >> 4;
    float acc[8][4];
#pragma unroll
    for (int i = 0; i < 8; i++)
#pragma unroll
        for (int j = 0; j < 4; j++) acc[i][j] = 0.f;
    for (int kk0 = 0; kk0 < kchunk; kk0 += 16) {
        float4 a0 = *(const float4*)(Ap + kk0);
        float4 a1 = *(const float4*)(Ap + kk0 + 4);
        float4 w0, w1;
        if (Wp) { w0 = *(const float4*)(Wp + kk0); w1 = *(const float4*)(Wp + kk0 + 4); }
        else    { w0 = make_float4(0,0,0,0); w1 = w0; }
        if (MODE == 1) {
            a0.x = sigm(a0.x); a0.y = sigm(a0.y); a0.z = sigm(a0.z); a0.w = sigm(a0.w);
            a1.x = sigm(a1.x); a1.y = sigm(a1.y); a1.z = sigm(a1.z); a1.w = sigm(a1.w);
        }
        __syncthreads();
        As[lk + 0][lr] = a0.x; As[lk + 1][lr] = a0.y; As[lk + 2][lr] = a0.z; As[lk + 3][lr] = a0.w;
        As[lk + 4][lr] = a1.x; As[lk + 5][lr] = a1.y; As[lk + 6][lr] = a1.z; As[lk + 7][lr] = a1.w;
        Ws[lk + 0][lr] = w0.x; Ws[lk + 1][lr] = w0.y; Ws[lk + 2][lr] = w0.z; Ws[lk + 3][lr] = w0.w;
        Ws[lk + 4][lr] = w1.x; Ws[lk + 5][lr] = w1.y; Ws[lk + 6][lr] = w1.z; Ws[lk + 7][lr] = w1.w;
        __syncthreads();
#pragma unroll
        for (int kk = 0; kk < 16; kk++) {
            float4 ra0 = *(const float4*)&As[kk][ty * 8];
            float4 ra1 = *(const float4*)&As[kk][ty * 8 + 4];
            float4 rw  = *(const float4*)&Ws[kk][tx * 4];
            acc[0][0] += ra0.x * rw.x; acc[0][1] += ra0.x * rw.y; acc[0][2] += ra0.x * rw.z; acc[0][3] += ra0.x * rw.w;
            acc[1][0] += ra0.y * rw.x; acc[1][1] += ra0.y * rw.y; acc[1][2] += ra0.y * rw.z; acc[1][3] += ra0.y * rw.w;
            acc[2][0] += ra0.z * rw.x; acc[2][1] += ra0.z * rw.y; acc[2][2] += ra0.z * rw.z; acc[2][3] += ra0.z * rw.w;
            acc[3][0] += ra0.w * rw.x; acc[3][1] += ra0.w * rw.y; acc[3][2] += ra0.w * rw.z; acc[3][3] += ra0.w * rw.w;
            acc[4][0] += ra1.x * rw.x; acc[4][1] += ra1.x * rw.y; acc[4][2] += ra1.x * rw.z; acc[4][3] += ra1.x * rw.w;
            acc[5][0] += ra1.y * rw.x; acc[5][1] += ra1.y * rw.y; acc[5][2] += ra1.y * rw.z; acc[5][3] += ra1.y * rw.w;
            acc[6][0] += ra1.z * rw.x; acc[6][1] += ra1.z * rw.y; acc[6][2] += ra1.z * rw.z; acc[6][3] += ra1.z * rw.w;
            acc[7][0] += ra1.w * rw.x; acc[7][1] += ra1.w * rw.y; acc[7][2] += ra1.w * rw.z; acc[7][3] += ra1.w * rw.w;
        }
    }
    float* Cb = C + (size_t)s * 64 * ldc;
#pragma unroll
    for (int i = 0; i < 8; i++) {
        const int mm = ty * 8 + i;
        const int n  = n0 + tx * 4;
        if (n < N) {
            float4 v = make_float4(acc[i][0], acc[i][1], acc[i][2], acc[i][3]);
            if (bias) {
                const float4 bv = *(const float4*)(bias + n);
                v.x += bv.x; v.y += bv.y; v.z += bv.z; v.w += bv.w;
            }
            *(float4*)(Cb + (size_t)mm * ldc + n) = v;
        }
    }
}

// ---------------- mean over P ----------------
__global__ void mean_k(const float* __restrict__ enc)
{
    const int idx = blockIdx.x * 256 + threadIdx.x;
    const int b = idx >> 11;
    const int e = idx & (ENC - 1);
    const float* p = enc + (size_t)b * P * ENC + e;
    float s = 0.f;
    for (int pp = 0; pp < P; pp++) s += p[(size_t)pp * ENC];
    g_mean[idx] = s * (1.f / (float)P);
}

// ---------------- reduce split-K partials + bias ----------------
__global__ void reduce_k(const float* __restrict__ part, int nsplit,
                         const float* __restrict__ bias, float* __restrict__ out, int N)
{
    const int idx = blockIdx.x * 256 + threadIdx.x;
    const int b = idx / N;
    const int n = idx - b * N;
    float s = bias[n];
    for (int ss = 0; ss < nsplit; ss++) s += part[(size_t)(ss * 64 + b) * N + n];
    out[idx] = s;
}

// ---------------- fused: att_h GEMV + scores + softmax (1 block / b) -------
__global__ void __launch_bounds__(256) scores_k(
    const float* __restrict__ Wh, const float* __restrict__ bh,
    const float* __restrict__ Wa, const float* __restrict__ ba)
{
    __shared__ float sh_hv[H];
    __shared__ float sh_h[A_DIM];
    __shared__ float sh_w[A_DIM];
    __shared__ float sc[256];
    __shared__ float red[256];
    const int b = blockIdx.x;
    const int tid = threadIdx.x;
    for (int i = tid; i < H; i += 256) sh_hv[i] = g_h[b * H + i];
    for (int i = tid; i < A_DIM; i += 256) sh_w[i] = Wa[i];
    __syncthreads();
    const int w = tid >> 5, lane = tid & 31;
    for (int a = w; a < A_DIM; a += 8) {
        const float* wr = Wh + (size_t)a * H;
        float s = 0.f;
#pragma unroll 4
        for (int k = lane; k < H; k += 32) s += sh_hv[k] * wr[k];
#pragma unroll
        for (int off = 16; off; off >>= 1) s += __shfl_xor_sync(0xffffffff, s, off);
        if (lane == 0) sh_h[a] = s + bh[a];
    }
    __syncthreads();
    for (int p = w; p < P; p += 8) {
        const float* row = g_att_enc + (size_t)(b * P + p) * A_DIM;
        float s = 0.f;
#pragma unroll 4
        for (int a = lane; a < A_DIM; a += 32) {
            const float v = row[a] + sh_h[a];
            s += fmaxf(v, 0.f) * sh_w[a];
        }
#pragma unroll
        for (int off = 16; off; off >>= 1) s += __shfl_xor_sync(0xffffffff, s, off);
        if (lane == 0) sc[p] = s + ba[0];
    }
    __syncthreads();
    const float v = (tid < P) ? sc[tid] : -FLT_MAX;
    red[tid] = v;
    __syncthreads();
    for (int off = 128; off; off >>= 1) { if (tid < off) red[tid] = fmaxf(red[tid], red[tid + off]); __syncthreads(); }
    const float mx = red[0];
    __syncthreads();
    const float e = (tid < P) ? expf(v - mx) : 0.f;
    red[tid] = e;
    __syncthreads();
    for (int off = 128; off; off >>= 1) { if (tid < off) red[tid] += red[tid + off]; __syncthreads(); }
    const float inv = 1.f / red[0];
    if (tid < P) g_alpha[b * P + tid] = e * inv;
}

// ---------------- weighted = alpha @ encode_out ----------------------------
__global__ void weighted_k(const float* __restrict__ enc)
{
    __shared__ float sa[P];
    const int b = blockIdx.y;
    const int e = blockIdx.x * 256 + threadIdx.x;
    if (threadIdx.x < P) sa[threadIdx.x] = g_alpha[b * P + threadIdx.x];
    __syncthreads();
    const float* base = enc + (size_t)b * P * ENC + e;
    float s = 0.f;
#pragma unroll 4
    for (int p = 0; p < P; p++) s += sa[p] * base[(size_t)p * ENC];
    g_weighted[b * ENC + e] = s;
}

// ---------------- build LSTM input ----------------
__global__ void mkinp_k(const float* __restrict__ emb, const int* __restrict__ cap,
                        const float* __restrict__ bg, int t)
{
    const int idx = blockIdx.x * 256 + threadIdx.x;
    const int b = idx / (E + ENC);
    const int j = idx - b * (E + ENC);
    float v;
    if (j < E) {
        const int tok = cap[b * T + t];
        v = emb[(size_t)tok * E + j];
    } else {
        const int j2 = j - E;
        float g = bg[j2];
#pragma unroll
        for (int ss = 0; ss < NS_GATE; ss++) g += g_part[(size_t)(ss * 64 + b) * ENC + j2];
        v = g_weighted[b * ENC + j2] * g;
    }
    g_inp[idx] = v;
}

// ---------------- LSTM cell (+ emits bf16 hi/lo of h) ----------------------
__global__ void lstm_k(const float* __restrict__ b_ih, const float* __restrict__ b_hh)
{
    const int idx = blockIdx.x * 256 + threadIdx.x;
    const int b = idx >> 9;
    const int n = idx & (H - 1);
    float gv[4];
#pragma unroll
    for (int q = 0; q < 4; q++) {
        const int pos = q * H + n;
        float s = b_ih[pos] + b_hh[pos];
#pragma unroll
        for (int ss = 0; ss < NS_GATES; ss++) s += g_part[(size_t)(ss * 64 + b) * (4 * H) + pos];
        gv[q] = s;
    }
    const float i_ = sigm(gv[0]);
    const float f_ = sigm(gv[1]);
    const float gg = tanhf(gv[2]);
    const float o_ = sigm(gv[3]);
    const float c  = f_ * g_c[idx] + i_ * gg;
    g_c[idx] = c;
    const float hv = o_ * tanhf(c);
    g_h[idx] = hv;
    const __nv_bfloat16 hh = __float2bfloat16(hv);
    g_h_hi[idx] = hh;
    g_h_lo[idx] = __float2bfloat16(hv - __bfloat162float(hh));
}

// ---------------- zero the final time step ----------------
__global__ void zero_k(float* __restrict__ out)
{
    const int idx = blockIdx.x * 256 + threadIdx.x;
    if (idx < B * V) {
        const int b = idx / V;
        const int n = idx - b * V;
        out[(size_t)b * T * V + (size_t)(T - 1) * V + n] = 0.f;
    }
}

// ---------------- launch ----------------
extern "C" void kernel_launch(void* const* d_in, const int* in_sizes, int n_in,
                              void* d_out, int out_size)
{
    const float* enc  = (const float*)d_in[0];
    const int*   cap  = (const int*)d_in[1];
    const float* emb  = (const float*)d_in[2];
    const float* W_ih = (const float*)d_in[3];
    const float* b_ih = (const float*)d_in[4];
    const float* W_hh = (const float*)d_in[5];
    const float* b_hh = (const float*)d_in[6];
    const float* We   = (const float*)d_in[7];
    const float* be   = (const float*)d_in[8];
    const float* Wh   = (const float*)d_in[9];
    const float* bh   = (const float*)d_in[10];
    const float* Wa   = (const float*)d_in[11];
    const float* ba   = (const float*)d_in[12];
    const float* Wch  = (const float*)d_in[13];
    const float* bch  = (const float*)d_in[14];
    const float* Wcc  = (const float*)d_in[15];
    const float* bcc  = (const float*)d_in[16];
    const float* Wfc  = (const float*)d_in[17];
    const float* bfc  = (const float*)d_in[18];
    const float* Wg   = (const float*)d_in[19];
    const float* bg   = (const float*)d_in[20];
    float* out = (float*)d_out;

    cudaFuncSetAttribute(hmma_k<128>, cudaFuncAttributeMaxDynamicSharedMemorySize, 65536);
    cudaFuncSetAttribute(hmma_k<64>,  cudaFuncAttributeMaxDynamicSharedMemorySize, 49152);

    float *p_att_enc, *p_part, *p_mean, *p_h, *p_c, *p_inp;
    __nv_bfloat16 *p_enc_hi, *p_enc_lo, *p_We_hi, *p_We_lo, *p_Wfc_hi, *p_Wfc_lo, *p_h_hi, *p_h_lo;
    cudaGetSymbolAddress((void**)&p_att_enc, g_att_enc);
    cudaGetSymbolAddress((void**)&p_part,    g_part);
    cudaGetSymbolAddress((void**)&p_mean,    g_mean);
    cudaGetSymbolAddress((void**)&p_h,       g_h);
    cudaGetSymbolAddress((void**)&p_c,       g_c);
    cudaGetSymbolAddress((void**)&p_inp,     g_inp);
    cudaGetSymbolAddress((void**)&p_enc_hi,  g_enc_hi);
    cudaGetSymbolAddress((void**)&p_enc_lo,  g_enc_lo);
    cudaGetSymbolAddress((void**)&p_We_hi,   g_We_hi);
    cudaGetSymbolAddress((void**)&p_We_lo,   g_We_lo);
    cudaGetSymbolAddress((void**)&p_Wfc_hi,  g_Wfc_hi);
    cudaGetSymbolAddress((void**)&p_Wfc_lo,  g_Wfc_lo);
    cudaGetSymbolAddress((void**)&p_h_hi,    g_h_hi);
    cudaGetSymbolAddress((void**)&p_h_lo,    g_h_lo);

    // ---- setup: bf16 splits ----
    split_k<<<(B * P * ENC + 255) / 256, 256>>>(enc, p_enc_hi, p_enc_lo, B * P * ENC);
    split_k<<<(A_DIM * ENC + 255) / 256, 256>>>(We, p_We_hi, p_We_lo, A_DIM * ENC);
    split_k<<<(V * H + 255) / 256, 256>>>(Wfc, p_Wfc_hi, p_Wfc_lo, V * H);

    // ---- setup: mean, h0/c0 ----
    mean_k<<<(B * ENC) / 256, 256>>>(enc);
    gemm64_k<0><<<dim3(H / 64, NS_HC), 128>>>(p_mean, ENC, nullptr, 0, Wch, ENC, nullptr, 0, 0,
                                              nullptr, p_part, H, H, ENC / NS_HC);
    reduce_k<<<(B * H) / 256, 256>>>(p_part, NS_HC, bch, p_h, H);
    gemm64_k<0><<<dim3(H / 64, NS_HC), 128>>>(p_mean, ENC, nullptr, 0, Wcc, ENC, nullptr, 0, 0,
                                              nullptr, p_part, H, H, ENC / NS_HC);
    reduce_k<<<(B * H) / 256, 256>>>(p_part, NS_HC, bcc, p_c, H);

    // ---- att_enc = encode_out @ We^T + be  (tensor cores, grid 4 x 98) ----
    hmma_k<128><<<dim3(A_DIM / 128, (B * P) / 128), 256, 65536>>>(
        p_enc_hi, p_enc_lo, p_We_hi, p_We_lo, be, p_att_enc, A_DIM, ENC, A_DIM, B * P);

    // ---- time loop ----
    for (int t = 0; t < T - 1; t++) {
        scores_k<<<B, 256>>>(Wh, bh, Wa, ba);
        weighted_k<<<dim3(ENC / 256, B), 256>>>(enc);
        gemm64_k<1><<<dim3(ENC / 64, NS_GATE), 128>>>(p_h, H, nullptr, 0, Wg, H, nullptr, 0, 0,
                                                      nullptr, p_part, ENC, ENC, H / NS_GATE);
        mkinp_k<<<(B * (E + ENC)) / 256, 256>>>(emb, cap, bg, t);
        gemm64_k<2><<<dim3((4 * H) / 64, NS_GATES), 128>>>(p_inp, E + ENC, p_h, H,
                                                           W_ih, E + ENC, W_hh, H, E + ENC,
                                                           nullptr, p_part, 4 * H, 4 * H, 256);
        lstm_k<<<(B * H) / 256, 256>>>(b_ih, b_hh);
        // pred = h @ Wfc^T + bfc  (tensor cores, BM=64, grid 235)
        hmma_k<64><<<dim3((V + 127) / 128, 1), 256, 49152>>>(
            p_h_hi, p_h_lo, p_Wfc_hi, p_Wfc_lo, bfc, out + (size_t)t * V, (long long)T * V,
            H, V, B);
    }
    zero_k<<<(B * V + 255) / 256, 256>>>(out);
}